// round 1
// baseline (speedup 1.0000x reference)
#include <cuda_runtime.h>
#include <cstdint>

// ---------------------------------------------------------------------------
// Problem constants: b=4, n=8192, dim=512, h=8, w=256, d=64
//   tokens T = 32768, windows = 128 (never cross batch since 256 | 8192)
// Inputs (metadata order): x[T,512], Wqkv[512,1536], bqkv[1536],
//                          Wproj[512,512], bproj[512], attn_bias[8,256,256]
// Output: [T,512] fp32
// ---------------------------------------------------------------------------

__device__ float g_qkv[32768ull * 1536];   // 192 MB scratch: qkv projections
__device__ float g_att[32768ull * 512];    // 64 MB scratch: attention output

// ---- packed fp32x2 helpers (FFMA2: 2x FMA throughput on sm_103a) ----------
__device__ __forceinline__ unsigned long long pack2(float lo, float hi) {
    unsigned long long r;
    asm("mov.b64 %0, {%1,%2};" : "=l"(r) : "f"(lo), "f"(hi));
    return r;
}
__device__ __forceinline__ unsigned long long fma2(unsigned long long a,
                                                   unsigned long long b,
                                                   unsigned long long c) {
    unsigned long long d;
    asm("fma.rn.f32x2 %0, %1, %2, %3;" : "=l"(d) : "l"(a), "l"(b), "l"(c));
    return d;
}
__device__ __forceinline__ float2 unpack2(unsigned long long v) {
    float2 f;
    asm("mov.b64 {%0,%1}, %2;" : "=f"(f.x), "=f"(f.y) : "l"(v));
    return f;
}

// ---------------------------------------------------------------------------
// SGEMM: C[M,N] = A[M,K] @ B[K,N] + bias[N]   (all row-major, fp32)
// 128x128 block tile, BK=16, 256 threads, 8x8 per thread, f32x2 accumulators.
// M,N,K all multiples of tile sizes here (no bounds checks).
// ---------------------------------------------------------------------------
#define BM 128
#define BN 128
#define BK 16
#define ASTR 132   // padded stride for As (multiple of 4 for float4 reads)

__global__ __launch_bounds__(256, 2)
void sgemm_bias_kernel(const float* __restrict__ A, const float* __restrict__ B,
                       const float* __restrict__ bias, float* __restrict__ C,
                       int M, int N, int K)
{
    __shared__ float As[BK * ASTR];   // As[k][m] (transposed)
    __shared__ float Bs[BK * BN];     // Bs[k][n]

    const int tid  = threadIdx.x;
    const int row0 = blockIdx.y * BM;
    const int col0 = blockIdx.x * BN;
    const int ty = tid >> 4;   // 0..15 -> rows ty*8..ty*8+7
    const int tx = tid & 15;   // 0..15 -> cols tx*8..tx*8+7

    const int am = tid >> 2;   // 0..63
    const int ac = tid & 3;    // 0..3
    const int bk = tid >> 5;   // 0..7
    const int bc = tid & 31;   // 0..31

    const float* Ap0 = A + (size_t)(row0 + am) * K + ac * 4;
    const float* Ap1 = A + (size_t)(row0 + am + 64) * K + ac * 4;
    const float* Bp0 = B + (size_t)bk * N + col0 + bc * 4;
    const float* Bp1 = B + (size_t)(bk + 8) * N + col0 + bc * 4;

    unsigned long long acc[8][4];
#pragma unroll
    for (int i = 0; i < 8; ++i)
#pragma unroll
        for (int j = 0; j < 4; ++j) acc[i][j] = 0ull;

    for (int k0 = 0; k0 < K; k0 += BK) {
        const float4 a0 = *(const float4*)(Ap0 + k0);
        const float4 a1 = *(const float4*)(Ap1 + k0);
        const float4 b0 = *(const float4*)(Bp0 + (size_t)k0 * N);
        const float4 b1 = *(const float4*)(Bp1 + (size_t)k0 * N);
        __syncthreads();
        As[(ac * 4 + 0) * ASTR + am] = a0.x;
        As[(ac * 4 + 1) * ASTR + am] = a0.y;
        As[(ac * 4 + 2) * ASTR + am] = a0.z;
        As[(ac * 4 + 3) * ASTR + am] = a0.w;
        As[(ac * 4 + 0) * ASTR + am + 64] = a1.x;
        As[(ac * 4 + 1) * ASTR + am + 64] = a1.y;
        As[(ac * 4 + 2) * ASTR + am + 64] = a1.z;
        As[(ac * 4 + 3) * ASTR + am + 64] = a1.w;
        *(float4*)(Bs + bk * BN + bc * 4)       = b0;
        *(float4*)(Bs + (bk + 8) * BN + bc * 4) = b1;
        __syncthreads();
#pragma unroll
        for (int kk = 0; kk < BK; ++kk) {
            const float4 af0 = *(const float4*)(As + kk * ASTR + ty * 8);
            const float4 af1 = *(const float4*)(As + kk * ASTR + ty * 8 + 4);
            const ulonglong2 bb0 = *(const ulonglong2*)(Bs + kk * BN + tx * 8);
            const ulonglong2 bb1 = *(const ulonglong2*)(Bs + kk * BN + tx * 8 + 4);
            const float a[8] = {af0.x, af0.y, af0.z, af0.w,
                                af1.x, af1.y, af1.z, af1.w};
#pragma unroll
            for (int i = 0; i < 8; ++i) {
                const unsigned long long a2 = pack2(a[i], a[i]);
                acc[i][0] = fma2(a2, bb0.x, acc[i][0]);
                acc[i][1] = fma2(a2, bb0.y, acc[i][1]);
                acc[i][2] = fma2(a2, bb1.x, acc[i][2]);
                acc[i][3] = fma2(a2, bb1.y, acc[i][3]);
            }
        }
    }

    float bias8[8];
    *(float4*)(bias8)     = *(const float4*)(bias + col0 + tx * 8);
    *(float4*)(bias8 + 4) = *(const float4*)(bias + col0 + tx * 8 + 4);

#pragma unroll
    for (int i = 0; i < 8; ++i) {
        float o[8];
#pragma unroll
        for (int j = 0; j < 4; ++j) {
            const float2 f = unpack2(acc[i][j]);
            o[2 * j]     = f.x + bias8[2 * j];
            o[2 * j + 1] = f.y + bias8[2 * j + 1];
        }
        float* cp = C + (size_t)(row0 + ty * 8 + i) * N + col0 + tx * 8;
        *(float4*)cp       = make_float4(o[0], o[1], o[2], o[3]);
        *(float4*)(cp + 4) = make_float4(o[4], o[5], o[6], o[7]);
    }
}

// ---------------------------------------------------------------------------
// Block-local attention. One block per (window, head): 128 windows x 8 heads.
// 256 threads. smem: Qt[64][64] (d-major), Kt[64][256] (d-major),
// Vs[256][64], Ps[64][260] (padded). 214016 bytes dynamic smem.
// qkv layout: token t, column = sel*512 + head*64 + d (sel: 0=q,1=k,2=v).
// ---------------------------------------------------------------------------
#define PSTR 260
#define ATT_SMEM_BYTES ((4096 + 16384 + 16384 + 64 * PSTR) * 4)

__global__ __launch_bounds__(256, 1)
void attn_kernel(const float* __restrict__ qkv, const float* __restrict__ bias,
                 float* __restrict__ out)
{
    extern __shared__ float sm[];
    float* Qt = sm;             // [64][64]   Qt[d][r]
    float* Kt = sm + 4096;      // [64][256]  Kt[d][key]
    float* Vs = Kt + 16384;     // [256][64]  Vs[key][d]
    float* Ps = Vs + 16384;     // [64][260]  Ps[r][key] (padded)

    const int tid   = threadIdx.x;
    const int head  = blockIdx.x & 7;
    const int win   = blockIdx.x >> 3;
    const int tbase = win * 256;
    const float scale = 0.125f;   // 64^-0.5

    // ---- load K transposed: each thread owns one key row ----
    {
        const float* kp = qkv + (size_t)(tbase + tid) * 1536 + 512 + head * 64;
#pragma unroll
        for (int it = 0; it < 16; ++it) {
            const float4 kv = *(const float4*)(kp + it * 4);
            Kt[(it * 4 + 0) * 256 + tid] = kv.x;
            Kt[(it * 4 + 1) * 256 + tid] = kv.y;
            Kt[(it * 4 + 2) * 256 + tid] = kv.z;
            Kt[(it * 4 + 3) * 256 + tid] = kv.w;
        }
    }
    // ---- load V (key-major, coalesced) ----
    {
        const float* vbase = qkv + (size_t)tbase * 1536 + 1024 + head * 64;
#pragma unroll
        for (int it = 0; it < 16; ++it) {
            const int idx = it * 256 + tid;
            const int key = idx >> 4, d4 = idx & 15;
            *(float4*)(Vs + key * 64 + d4 * 4) =
                *(const float4*)(vbase + (size_t)key * 1536 + d4 * 4);
        }
    }

    const int wi  = tid >> 5;          // warp id: owns q-rows wi*8..wi*8+7
    const int l   = tid & 31;          // lane: owns keys l*8..l*8+7
    const int r04 = (tid >> 4) << 2;   // phase2: rows r04..r04+3
    const int dd4 = tid & 15;          // phase2: dims dd4*4..dd4*4+3

    for (int qt = 0; qt < 4; ++qt) {
        __syncthreads();   // prev phase2 done reading Ps; (qt=0: K/V loads done)

        // ---- load Q tile transposed ----
        {
            const int r  = tid & 63;
            const int dh = tid >> 6;   // 0..3
            const float* qp = qkv + (size_t)(tbase + qt * 64 + r) * 1536 + head * 64;
#pragma unroll
            for (int it = 0; it < 4; ++it) {
                const int d4 = it * 4 + dh;
                const float4 q = *(const float4*)(qp + d4 * 4);
                Qt[(d4 * 4 + 0) * 64 + r] = q.x;
                Qt[(d4 * 4 + 1) * 64 + r] = q.y;
                Qt[(d4 * 4 + 2) * 64 + r] = q.z;
                Qt[(d4 * 4 + 3) * 64 + r] = q.w;
            }
        }
        __syncthreads();

        // ---- phase 1: S = Q K^T  (8 rows x 8 keys per thread, f32x2) ----
        unsigned long long acc[8][4];
#pragma unroll
        for (int i = 0; i < 8; ++i)
#pragma unroll
            for (int j = 0; j < 4; ++j) acc[i][j] = 0ull;

#pragma unroll 8
        for (int d = 0; d < 64; ++d) {
            const float4 qa = *(const float4*)(Qt + d * 64 + wi * 8);
            const float4 qb = *(const float4*)(Qt + d * 64 + wi * 8 + 4);
            const ulonglong2 ka = *(const ulonglong2*)(Kt + d * 256 + l * 8);
            const ulonglong2 kb = *(const ulonglong2*)(Kt + d * 256 + l * 8 + 4);
            const float q[8] = {qa.x, qa.y, qa.z, qa.w, qb.x, qb.y, qb.z, qb.w};
#pragma unroll
            for (int i = 0; i < 8; ++i) {
                const unsigned long long q2 = pack2(q[i], q[i]);
                acc[i][0] = fma2(q2, ka.x, acc[i][0]);
                acc[i][1] = fma2(q2, ka.y, acc[i][1]);
                acc[i][2] = fma2(q2, kb.x, acc[i][2]);
                acc[i][3] = fma2(q2, kb.y, acc[i][3]);
            }
        }

        // ---- bias + softmax (per-row, full-warp shuffle reduce) ----
        const float* bh = bias + head * 65536 + (qt * 64 + wi * 8) * 256 + l * 8;
#pragma unroll
        for (int i = 0; i < 8; ++i) {
            const float4 b0 = *(const float4*)(bh + i * 256);
            const float4 b1 = *(const float4*)(bh + i * 256 + 4);
            const float2 f0 = unpack2(acc[i][0]);
            const float2 f1 = unpack2(acc[i][1]);
            const float2 f2 = unpack2(acc[i][2]);
            const float2 f3 = unpack2(acc[i][3]);
            float s[8];
            s[0] = f0.x * scale + b0.x;  s[1] = f0.y * scale + b0.y;
            s[2] = f1.x * scale + b0.z;  s[3] = f1.y * scale + b0.w;
            s[4] = f2.x * scale + b1.x;  s[5] = f2.y * scale + b1.y;
            s[6] = f3.x * scale + b1.z;  s[7] = f3.y * scale + b1.w;

            float m = s[0];
#pragma unroll
            for (int j = 1; j < 8; ++j) m = fmaxf(m, s[j]);
#pragma unroll
            for (int o = 16; o > 0; o >>= 1)
                m = fmaxf(m, __shfl_xor_sync(0xffffffffu, m, o));

            float sum = 0.0f;
#pragma unroll
            for (int j = 0; j < 8; ++j) { s[j] = __expf(s[j] - m); sum += s[j]; }
#pragma unroll
            for (int o = 16; o > 0; o >>= 1)
                sum += __shfl_xor_sync(0xffffffffu, sum, o);
            const float inv = 1.0f / sum;

            float* pr = Ps + (wi * 8 + i) * PSTR + l * 8;
            *(float4*)pr       = make_float4(s[0] * inv, s[1] * inv, s[2] * inv, s[3] * inv);
            *(float4*)(pr + 4) = make_float4(s[4] * inv, s[5] * inv, s[6] * inv, s[7] * inv);
        }
        __syncthreads();

        // ---- phase 2: O = P V  (4 rows x 4 dims per thread, f32x2) ----
        unsigned long long o2[4][2];
#pragma unroll
        for (int i = 0; i < 4; ++i) { o2[i][0] = 0ull; o2[i][1] = 0ull; }

#pragma unroll 8
        for (int kc = 0; kc < 64; ++kc) {
            float4 p[4];
#pragma unroll
            for (int ii = 0; ii < 4; ++ii)
                p[ii] = *(const float4*)(Ps + (r04 + ii) * PSTR + kc * 4);
            ulonglong2 v[4];
#pragma unroll
            for (int m = 0; m < 4; ++m)
                v[m] = *(const ulonglong2*)(Vs + (kc * 4 + m) * 64 + dd4 * 4);
#pragma unroll
            for (int ii = 0; ii < 4; ++ii) {
                unsigned long long pp;
                pp = pack2(p[ii].x, p[ii].x);
                o2[ii][0] = fma2(pp, v[0].x, o2[ii][0]);
                o2[ii][1] = fma2(pp, v[0].y, o2[ii][1]);
                pp = pack2(p[ii].y, p[ii].y);
                o2[ii][0] = fma2(pp, v[1].x, o2[ii][0]);
                o2[ii][1] = fma2(pp, v[1].y, o2[ii][1]);
                pp = pack2(p[ii].z, p[ii].z);
                o2[ii][0] = fma2(pp, v[2].x, o2[ii][0]);
                o2[ii][1] = fma2(pp, v[2].y, o2[ii][1]);
                pp = pack2(p[ii].w, p[ii].w);
                o2[ii][0] = fma2(pp, v[3].x, o2[ii][0]);
                o2[ii][1] = fma2(pp, v[3].y, o2[ii][1]);
            }
        }

        // ---- store O to [T,512] scratch (col = head*64 + d) ----
        float* ob = out + (size_t)(tbase + qt * 64 + r04) * 512 + head * 64 + dd4 * 4;
#pragma unroll
        for (int ii = 0; ii < 4; ++ii) {
            const float2 f0 = unpack2(o2[ii][0]);
            const float2 f1 = unpack2(o2[ii][1]);
            *(float4*)(ob + (size_t)ii * 512) = make_float4(f0.x, f0.y, f1.x, f1.y);
        }
    }
}

// ---------------------------------------------------------------------------
extern "C" void kernel_launch(void* const* d_in, const int* in_sizes, int n_in,
                              void* d_out, int out_size)
{
    const float* x     = (const float*)d_in[0];
    const float* Wqkv  = (const float*)d_in[1];
    const float* bqkv  = (const float*)d_in[2];
    const float* Wproj = (const float*)d_in[3];
    const float* bproj = (const float*)d_in[4];
    const float* abias = (const float*)d_in[5];
    float* out = (float*)d_out;

    float *qkv_ptr, *att_ptr;
    cudaGetSymbolAddress((void**)&qkv_ptr, g_qkv);
    cudaGetSymbolAddress((void**)&att_ptr, g_att);

    cudaFuncSetAttribute(attn_kernel,
                         cudaFuncAttributeMaxDynamicSharedMemorySize,
                         ATT_SMEM_BYTES);

    const dim3 threads(256);
    // QKV projection: [32768,512] @ [512,1536]
    sgemm_bias_kernel<<<dim3(12, 256), threads>>>(x, Wqkv, bqkv, qkv_ptr,
                                                  32768, 1536, 512);
    // Block-local attention: 128 windows x 8 heads
    attn_kernel<<<dim3(1024), threads, ATT_SMEM_BYTES>>>(qkv_ptr, abias, att_ptr);
    // Output projection: [32768,512] @ [512,512]
    sgemm_bias_kernel<<<dim3(4, 256), threads>>>(att_ptr, Wproj, bproj, out,
                                                 32768, 512, 512);
}

// round 4
// speedup vs baseline: 1.8402x; 1.8402x over previous
#include <cuda_runtime.h>
#include <cuda_bf16.h>
#include <cstdint>

// ---------------------------------------------------------------------------
// b=4, n=8192, dim=512, h=8, w=256, d=64.  T=32768 tokens, 128 windows.
// Inputs: x[T,512], Wqkv[512,1536], bqkv[1536], Wproj[512,512], bproj[512],
//         attn_bias[8,256,256].  Output [T,512] fp32.
//
// Pipeline:
//   split x -> bf16 hi/lo
//   transpose+split Wqkv, Wproj -> [N,K] bf16 hi/lo
//   GEMM1 (mma.sync bf16 3-product split): qkv = x @ Wqkv + bqkv (fp32)
//   attention (fp32 FFMA2) -> att hi/lo bf16
//   GEMM2 (mma.sync): out = att @ Wproj + bproj (fp32)
// ---------------------------------------------------------------------------

__device__ float          g_qkv[32768ull * 1536];
__device__ __nv_bfloat16  g_xhi[32768ull * 512],  g_xlo[32768ull * 512];
__device__ __nv_bfloat16  g_ahi[32768ull * 512],  g_alo[32768ull * 512];
__device__ __nv_bfloat16  g_wqhi[1536ull * 512],  g_wqlo[1536ull * 512];
__device__ __nv_bfloat16  g_wphi[512ull * 512],   g_wplo[512ull * 512];

// ---------------- helpers ---------------------------------------------------
__device__ __forceinline__ uint32_t smem_u32(const void* p) {
    uint32_t a;
    asm("{ .reg .u64 t; cvta.to.shared.u64 t, %1; cvt.u32.u64 %0, t; }"
        : "=r"(a) : "l"(p));
    return a;
}
#define SWZ128(x) ((x) ^ (((x) >> 3) & 0x70))

__device__ __forceinline__ void cpa16(uint32_t dst, const void* src) {
    asm volatile("cp.async.cg.shared.global [%0], [%1], 16;"
                 :: "r"(dst), "l"(src) : "memory");
}
template <int N>
__device__ __forceinline__ void cp_wait() {
    asm volatile("cp.async.wait_group %0;" :: "n"(N) : "memory");
}

#define LDSM_X4(r, addr)                                                      \
    asm volatile("ldmatrix.sync.aligned.m8n8.x4.shared.b16 {%0,%1,%2,%3}, [%4];" \
                 : "=r"((r)[0]), "=r"((r)[1]), "=r"((r)[2]), "=r"((r)[3])     \
                 : "r"(addr))

#define MMA_BF16(d, a, b0, b1)                                                \
    asm volatile("mma.sync.aligned.m16n8k16.row.col.f32.bf16.bf16.f32 "       \
                 "{%0,%1,%2,%3}, {%4,%5,%6,%7}, {%8,%9}, {%0,%1,%2,%3};"      \
                 : "+f"((d)[0]), "+f"((d)[1]), "+f"((d)[2]), "+f"((d)[3])     \
                 : "r"((a)[0]), "r"((a)[1]), "r"((a)[2]), "r"((a)[3]),        \
                   "r"(b0), "r"(b1))

// ---- packed fp32x2 (attention) ----
__device__ __forceinline__ unsigned long long pack2(float lo, float hi) {
    unsigned long long r;
    asm("mov.b64 %0, {%1,%2};" : "=l"(r) : "f"(lo), "f"(hi));
    return r;
}
__device__ __forceinline__ unsigned long long fma2(unsigned long long a,
                                                   unsigned long long b,
                                                   unsigned long long c) {
    unsigned long long d;
    asm("fma.rn.f32x2 %0, %1, %2, %3;" : "=l"(d) : "l"(a), "l"(b), "l"(c));
    return d;
}
__device__ __forceinline__ float2 unpack2(unsigned long long v) {
    float2 f;
    asm("mov.b64 {%0,%1}, %2;" : "=f"(f.x), "=f"(f.y) : "l"(v));
    return f;
}

// ---------------------------------------------------------------------------
// split x (fp32) -> hi/lo bf16
// ---------------------------------------------------------------------------
__global__ void split_kernel(const float* __restrict__ in,
                             __nv_bfloat16* __restrict__ hi,
                             __nv_bfloat16* __restrict__ lo, int n4)
{
    int i = blockIdx.x * blockDim.x + threadIdx.x;
    if (i >= n4) return;
    float4 v = ((const float4*)in)[i];
    __nv_bfloat16 h0 = __float2bfloat16(v.x), h1 = __float2bfloat16(v.y);
    __nv_bfloat16 h2 = __float2bfloat16(v.z), h3 = __float2bfloat16(v.w);
    __nv_bfloat16 l0 = __float2bfloat16(v.x - __bfloat162float(h0));
    __nv_bfloat16 l1 = __float2bfloat16(v.y - __bfloat162float(h1));
    __nv_bfloat16 l2 = __float2bfloat16(v.z - __bfloat162float(h2));
    __nv_bfloat16 l3 = __float2bfloat16(v.w - __bfloat162float(h3));
    __nv_bfloat162* hp = (__nv_bfloat162*)(hi + (size_t)i * 4);
    __nv_bfloat162* lp = (__nv_bfloat162*)(lo + (size_t)i * 4);
    hp[0] = {h0, h1}; hp[1] = {h2, h3};
    lp[0] = {l0, l1}; lp[1] = {l2, l3};
}

// ---------------------------------------------------------------------------
// transpose W[K,N] -> Wt[N,K] split into hi/lo bf16
// ---------------------------------------------------------------------------
__global__ void tsplit_kernel(const float* __restrict__ W,
                              __nv_bfloat16* __restrict__ thi,
                              __nv_bfloat16* __restrict__ tlo, int K, int N)
{
    __shared__ float t[32][33];
    const int kx = blockIdx.y * 32, nx = blockIdx.x * 32;
    const int lx = threadIdx.x & 31, ly = threadIdx.x >> 5;
#pragma unroll
    for (int j = 0; j < 32; j += 8)
        t[ly + j][lx] = W[(size_t)(kx + ly + j) * N + nx + lx];
    __syncthreads();
#pragma unroll
    for (int j = 0; j < 32; j += 8) {
        float v = t[lx][ly + j];
        __nv_bfloat16 h = __float2bfloat16(v);
        __nv_bfloat16 l = __float2bfloat16(v - __bfloat162float(h));
        thi[(size_t)(nx + ly + j) * K + kx + lx] = h;
        tlo[(size_t)(nx + ly + j) * K + kx + lx] = l;
    }
}

// ---------------------------------------------------------------------------
// mma.sync GEMM: C[M,N] = A[M,512] @ Bt[N,512]^T + bias, fp32 out.
// 128x128 tile, Kc=64 chunks, double-buffered cp.async, 8 warps (32x64 each).
// Three bf16 MMAs per logical fp32 MAC-tile: AhBh + AhBl + AlBh.
// grid = (N/128, M/128), 256 threads, 128KB dynamic smem.
// ---------------------------------------------------------------------------
#define GK        512
#define KC        64
#define NCHUNK    (GK / KC)
#define STAGE     65536                 // Ahi16K + Alo16K + Bhi16K + Blo16K
#define GM_SMEM   (2 * STAGE)

__global__ __launch_bounds__(256, 1)
void gemm_mma(const __nv_bfloat16* __restrict__ Ahi,
              const __nv_bfloat16* __restrict__ Alo,
              const __nv_bfloat16* __restrict__ Bhi,
              const __nv_bfloat16* __restrict__ Blo,
              const float* __restrict__ bias, float* __restrict__ C, int N)
{
    extern __shared__ char sm[];
    const uint32_t sb = smem_u32(sm);
    const int tid = threadIdx.x, wid = tid >> 5, lane = tid & 31;
    const int wm = wid & 3, wn = wid >> 2;            // warp tile: 32 x 64
    const int m0 = blockIdx.y * 128, n0 = blockIdx.x * 128;

    auto load_chunk = [&](int c, int buf) {
        const int k0 = c * KC;
        const uint32_t base = sb + buf * STAGE;
#pragma unroll
        for (int it = 0; it < 4; ++it) {
            const int op = it * 256 + tid;
            const int r = op >> 3, g = op & 7;
            const uint32_t off = SWZ128((uint32_t)(r * 128 + g * 16));
            const size_t giA = (size_t)(m0 + r) * GK + k0 + g * 8;
            const size_t giB = (size_t)(n0 + r) * GK + k0 + g * 8;
            cpa16(base + off,         Ahi + giA);
            cpa16(base + 16384 + off, Alo + giA);
            cpa16(base + 32768 + off, Bhi + giB);
            cpa16(base + 49152 + off, Blo + giB);
        }
        asm volatile("cp.async.commit_group;" ::: "memory");
    };

    float acc[2][8][4];
#pragma unroll
    for (int i = 0; i < 2; ++i)
#pragma unroll
        for (int j = 0; j < 8; ++j)
#pragma unroll
            for (int k = 0; k < 4; ++k) acc[i][j][k] = 0.0f;

    // ldmatrix lane->address components
    const int a_row = wm * 32 + (lane & 15);          // + mt*16
    const int a_kb  = (lane >> 4) * 16;               // + g*32
    const int b_row = wn * 64 + (lane & 7) + ((lane >> 4) << 3);  // + np*16
    const int b_kb  = ((lane >> 3) & 1) * 16;         // + g*32

    load_chunk(0, 0);

    for (int c = 0; c < NCHUNK; ++c) {
        if (c < NCHUNK - 1) { load_chunk(c + 1, (c + 1) & 1); cp_wait<1>(); }
        else                { cp_wait<0>(); }
        __syncthreads();

        const uint32_t bufb = sb + (c & 1) * STAGE;
#pragma unroll
        for (int g = 0; g < 4; ++g) {
            uint32_t ah[2][4], al[2][4];
#pragma unroll
            for (int mt = 0; mt < 2; ++mt) {
                const uint32_t offA =
                    SWZ128((uint32_t)((a_row + mt * 16) * 128 + g * 32 + a_kb));
                LDSM_X4(ah[mt], bufb + offA);
                LDSM_X4(al[mt], bufb + 16384 + offA);
            }
#pragma unroll
            for (int np = 0; np < 4; ++np) {
                const uint32_t offB =
                    SWZ128((uint32_t)((b_row + np * 16) * 128 + g * 32 + b_kb));
                uint32_t bh[4], bl[4];
                LDSM_X4(bh, bufb + 32768 + offB);
                LDSM_X4(bl, bufb + 49152 + offB);
#pragma unroll
                for (int mt = 0; mt < 2; ++mt) {
                    MMA_BF16(acc[mt][np * 2 + 0], ah[mt], bh[0], bh[1]);
                    MMA_BF16(acc[mt][np * 2 + 0], ah[mt], bl[0], bl[1]);
                    MMA_BF16(acc[mt][np * 2 + 0], al[mt], bh[0], bh[1]);
                    MMA_BF16(acc[mt][np * 2 + 1], ah[mt], bh[2], bh[3]);
                    MMA_BF16(acc[mt][np * 2 + 1], ah[mt], bl[2], bl[3]);
                    MMA_BF16(acc[mt][np * 2 + 1], al[mt], bh[2], bh[3]);
                }
            }
        }
        __syncthreads();
    }

    // ---- epilogue: fragment -> GMEM with bias ----
    const int er = lane >> 2, ec = (lane & 3) * 2;
#pragma unroll
    for (int mt = 0; mt < 2; ++mt) {
        const int row = m0 + wm * 32 + mt * 16 + er;
#pragma unroll
        for (int nt = 0; nt < 8; ++nt) {
            const int col = n0 + wn * 64 + nt * 8 + ec;
            const float2 bv = *(const float2*)(bias + col);
            float2 o0, o1;
            o0.x = acc[mt][nt][0] + bv.x;  o0.y = acc[mt][nt][1] + bv.y;
            o1.x = acc[mt][nt][2] + bv.x;  o1.y = acc[mt][nt][3] + bv.y;
            *(float2*)(C + (size_t)row * N + col)       = o0;
            *(float2*)(C + (size_t)(row + 8) * N + col) = o1;
        }
    }
}

// ---------------------------------------------------------------------------
// Block-local attention (fp32 FFMA2), epilogue emits bf16 hi/lo for proj.
// ---------------------------------------------------------------------------
#define PSTR 260
#define ATT_SMEM_BYTES ((4096 + 16384 + 16384 + 64 * PSTR) * 4)

__global__ __launch_bounds__(256, 1)
void attn_kernel(const float* __restrict__ qkv, const float* __restrict__ bias,
                 __nv_bfloat16* __restrict__ ohi, __nv_bfloat16* __restrict__ olo)
{
    extern __shared__ float smf[];
    float* Qt = smf;            // [64][64]
    float* Kt = smf + 4096;     // [64][256]
    float* Vs = Kt + 16384;     // [256][64]
    float* Ps = Vs + 16384;     // [64][PSTR]

    const int tid   = threadIdx.x;
    const int head  = blockIdx.x & 7;
    const int win   = blockIdx.x >> 3;
    const int tbase = win * 256;
    const float scale = 0.125f;

    {
        const float* kp = qkv + (size_t)(tbase + tid) * 1536 + 512 + head * 64;
#pragma unroll
        for (int it = 0; it < 16; ++it) {
            const float4 kv = *(const float4*)(kp + it * 4);
            Kt[(it * 4 + 0) * 256 + tid] = kv.x;
            Kt[(it * 4 + 1) * 256 + tid] = kv.y;
            Kt[(it * 4 + 2) * 256 + tid] = kv.z;
            Kt[(it * 4 + 3) * 256 + tid] = kv.w;
        }
    }
    {
        const float* vbase = qkv + (size_t)tbase * 1536 + 1024 + head * 64;
#pragma unroll
        for (int it = 0; it < 16; ++it) {
            const int idx = it * 256 + tid;
            const int key = idx >> 4, d4 = idx & 15;
            *(float4*)(Vs + key * 64 + d4 * 4) =
                *(const float4*)(vbase + (size_t)key * 1536 + d4 * 4);
        }
    }

    const int wi  = tid >> 5;
    const int l   = tid & 31;
    const int r04 = (tid >> 4) << 2;
    const int dd4 = tid & 15;

    for (int qt = 0; qt < 4; ++qt) {
        __syncthreads();
        {
            const int r  = tid & 63;
            const int dh = tid >> 6;
            const float* qp = qkv + (size_t)(tbase + qt * 64 + r) * 1536 + head * 64;
#pragma unroll
            for (int it = 0; it < 4; ++it) {
                const int d4 = it * 4 + dh;
                const float4 q = *(const float4*)(qp + d4 * 4);
                Qt[(d4 * 4 + 0) * 64 + r] = q.x;
                Qt[(d4 * 4 + 1) * 64 + r] = q.y;
                Qt[(d4 * 4 + 2) * 64 + r] = q.z;
                Qt[(d4 * 4 + 3) * 64 + r] = q.w;
            }
        }
        __syncthreads();

        unsigned long long acc[8][4];
#pragma unroll
        for (int i = 0; i < 8; ++i)
#pragma unroll
            for (int j = 0; j < 4; ++j) acc[i][j] = 0ull;

#pragma unroll 8
        for (int d = 0; d < 64; ++d) {
            const float4 qa = *(const float4*)(Qt + d * 64 + wi * 8);
            const float4 qb = *(const float4*)(Qt + d * 64 + wi * 8 + 4);
            const ulonglong2 ka = *(const ulonglong2*)(Kt + d * 256 + l * 8);
            const ulonglong2 kb = *(const ulonglong2*)(Kt + d * 256 + l * 8 + 4);
            const float q[8] = {qa.x, qa.y, qa.z, qa.w, qb.x, qb.y, qb.z, qb.w};
#pragma unroll
            for (int i = 0; i < 8; ++i) {
                const unsigned long long q2 = pack2(q[i], q[i]);
                acc[i][0] = fma2(q2, ka.x, acc[i][0]);
                acc[i][1] = fma2(q2, ka.y, acc[i][1]);
                acc[i][2] = fma2(q2, kb.x, acc[i][2]);
                acc[i][3] = fma2(q2, kb.y, acc[i][3]);
            }
        }

        const float* bh = bias + head * 65536 + (qt * 64 + wi * 8) * 256 + l * 8;
#pragma unroll
        for (int i = 0; i < 8; ++i) {
            const float4 b0 = *(const float4*)(bh + i * 256);
            const float4 b1 = *(const float4*)(bh + i * 256 + 4);
            const float2 f0 = unpack2(acc[i][0]);
            const float2 f1 = unpack2(acc[i][1]);
            const float2 f2 = unpack2(acc[i][2]);
            const float2 f3 = unpack2(acc[i][3]);
            float s[8];
            s[0] = f0.x * scale + b0.x;  s[1] = f0.y * scale + b0.y;
            s[2] = f1.x * scale + b0.z;  s[3] = f1.y * scale + b0.w;
            s[4] = f2.x * scale + b1.x;  s[5] = f2.y * scale + b1.y;
            s[6] = f3.x * scale + b1.z;  s[7] = f3.y * scale + b1.w;

            float m = s[0];
#pragma unroll
            for (int j = 1; j < 8; ++j) m = fmaxf(m, s[j]);
#pragma unroll
            for (int o = 16; o > 0; o >>= 1)
                m = fmaxf(m, __shfl_xor_sync(0xffffffffu, m, o));

            float sum = 0.0f;
#pragma unroll
            for (int j = 0; j < 8; ++j) { s[j] = __expf(s[j] - m); sum += s[j]; }
#pragma unroll
            for (int o = 16; o > 0; o >>= 1)
                sum += __shfl_xor_sync(0xffffffffu, sum, o);
            const float inv = 1.0f / sum;

            float* pr = Ps + (wi * 8 + i) * PSTR + l * 8;
            *(float4*)pr       = make_float4(s[0] * inv, s[1] * inv, s[2] * inv, s[3] * inv);
            *(float4*)(pr + 4) = make_float4(s[4] * inv, s[5] * inv, s[6] * inv, s[7] * inv);
        }
        __syncthreads();

        unsigned long long o2[4][2];
#pragma unroll
        for (int i = 0; i < 4; ++i) { o2[i][0] = 0ull; o2[i][1] = 0ull; }

#pragma unroll 8
        for (int kc = 0; kc < 64; ++kc) {
            float4 p[4];
#pragma unroll
            for (int ii = 0; ii < 4; ++ii)
                p[ii] = *(const float4*)(Ps + (r04 + ii) * PSTR + kc * 4);
            ulonglong2 v[4];
#pragma unroll
            for (int m = 0; m < 4; ++m)
                v[m] = *(const ulonglong2*)(Vs + (kc * 4 + m) * 64 + dd4 * 4);
#pragma unroll
            for (int ii = 0; ii < 4; ++ii) {
                unsigned long long pp;
                pp = pack2(p[ii].x, p[ii].x);
                o2[ii][0] = fma2(pp, v[0].x, o2[ii][0]);
                o2[ii][1] = fma2(pp, v[0].y, o2[ii][1]);
                pp = pack2(p[ii].y, p[ii].y);
                o2[ii][0] = fma2(pp, v[1].x, o2[ii][0]);
                o2[ii][1] = fma2(pp, v[1].y, o2[ii][1]);
                pp = pack2(p[ii].z, p[ii].z);
                o2[ii][0] = fma2(pp, v[2].x, o2[ii][0]);
                o2[ii][1] = fma2(pp, v[2].y, o2[ii][1]);
                pp = pack2(p[ii].w, p[ii].w);
                o2[ii][0] = fma2(pp, v[3].x, o2[ii][0]);
                o2[ii][1] = fma2(pp, v[3].y, o2[ii][1]);
            }
        }

        const size_t eb = (size_t)(tbase + qt * 64 + r04) * 512 + head * 64 + dd4 * 4;
#pragma unroll
        for (int ii = 0; ii < 4; ++ii) {
            const float2 f0 = unpack2(o2[ii][0]);
            const float2 f1 = unpack2(o2[ii][1]);
            const float v[4] = {f0.x, f0.y, f1.x, f1.y};
            __nv_bfloat16 h[4], lo[4];
#pragma unroll
            for (int j = 0; j < 4; ++j) {
                h[j]  = __float2bfloat16(v[j]);
                lo[j] = __float2bfloat16(v[j] - __bfloat162float(h[j]));
            }
            __nv_bfloat162* hp = (__nv_bfloat162*)(ohi + eb + (size_t)ii * 512);
            __nv_bfloat162* lp = (__nv_bfloat162*)(olo + eb + (size_t)ii * 512);
            hp[0] = {h[0], h[1]};  hp[1] = {h[2], h[3]};
            lp[0] = {lo[0], lo[1]}; lp[1] = {lo[2], lo[3]};
        }
    }
}

// ---------------------------------------------------------------------------
extern "C" void kernel_launch(void* const* d_in, const int* in_sizes, int n_in,
                              void* d_out, int out_size)
{
    const float* x     = (const float*)d_in[0];
    const float* Wqkv  = (const float*)d_in[1];
    const float* bqkv  = (const float*)d_in[2];
    const float* Wproj = (const float*)d_in[3];
    const float* bproj = (const float*)d_in[4];
    const float* abias = (const float*)d_in[5];
    float* out = (float*)d_out;

    float *qkv_p;
    __nv_bfloat16 *xhi, *xlo, *ahi, *alo, *wqhi, *wqlo, *wphi, *wplo;
    cudaGetSymbolAddress((void**)&qkv_p, g_qkv);
    cudaGetSymbolAddress((void**)&xhi,  g_xhi);
    cudaGetSymbolAddress((void**)&xlo,  g_xlo);
    cudaGetSymbolAddress((void**)&ahi,  g_ahi);
    cudaGetSymbolAddress((void**)&alo,  g_alo);
    cudaGetSymbolAddress((void**)&wqhi, g_wqhi);
    cudaGetSymbolAddress((void**)&wqlo, g_wqlo);
    cudaGetSymbolAddress((void**)&wphi, g_wphi);
    cudaGetSymbolAddress((void**)&wplo, g_wplo);

    cudaFuncSetAttribute(gemm_mma, cudaFuncAttributeMaxDynamicSharedMemorySize,
                         GM_SMEM);
    cudaFuncSetAttribute(attn_kernel, cudaFuncAttributeMaxDynamicSharedMemorySize,
                         ATT_SMEM_BYTES);

    const int n4 = 32768 * 512 / 4;
    split_kernel<<<(n4 + 255) / 256, 256>>>(x, xhi, xlo, n4);
    tsplit_kernel<<<dim3(1536 / 32, 512 / 32), 256>>>(Wqkv, wqhi, wqlo, 512, 1536);
    tsplit_kernel<<<dim3(512 / 32, 512 / 32), 256>>>(Wproj, wphi, wplo, 512, 512);

    gemm_mma<<<dim3(12, 256), 256, GM_SMEM>>>(xhi, xlo, wqhi, wqlo, bqkv, qkv_p, 1536);
    attn_kernel<<<dim3(1024), 256, ATT_SMEM_BYTES>>>(qkv_p, abias, ahi, alo);
    gemm_mma<<<dim3(4, 256), 256, GM_SMEM>>>(ahi, alo, wphi, wplo, bproj, out, 512);
}

// round 5
// speedup vs baseline: 2.2720x; 1.2346x over previous
#include <cuda_runtime.h>
#include <cuda_bf16.h>
#include <cstdint>

// ---------------------------------------------------------------------------
// b=4, n=8192, dim=512, h=8, w=256, d=64.  T=32768 tokens, 128 windows.
// Pipeline (all matmuls on tensor cores, bf16 hi/lo 3-product split, fp32 acc):
//   split x -> bf16 hi/lo ; transpose+split weights
//   GEMM1: qkv(hi/lo bf16) = x @ Wqkv + bqkv
//   attention (mma.sync QK^T + PV, softmax on fragments) -> att hi/lo bf16
//   GEMM2: out(fp32) = att @ Wproj + bproj
// ---------------------------------------------------------------------------

__device__ __nv_bfloat16  g_qkvhi[32768ull * 1536], g_qkvlo[32768ull * 1536];
__device__ __nv_bfloat16  g_xhi[32768ull * 512],  g_xlo[32768ull * 512];
__device__ __nv_bfloat16  g_ahi[32768ull * 512],  g_alo[32768ull * 512];
__device__ __nv_bfloat16  g_wqhi[1536ull * 512],  g_wqlo[1536ull * 512];
__device__ __nv_bfloat16  g_wphi[512ull * 512],   g_wplo[512ull * 512];

// ---------------- helpers ---------------------------------------------------
__device__ __forceinline__ uint32_t smem_u32(const void* p) {
    uint32_t a;
    asm("{ .reg .u64 t; cvta.to.shared.u64 t, %1; cvt.u32.u64 %0, t; }"
        : "=r"(a) : "l"(p));
    return a;
}
#define SWZ128(x) ((x) ^ (((x) >> 3) & 0x70))

__device__ __forceinline__ void cpa16(uint32_t dst, const void* src) {
    asm volatile("cp.async.cg.shared.global [%0], [%1], 16;"
                 :: "r"(dst), "l"(src) : "memory");
}
template <int N>
__device__ __forceinline__ void cp_wait() {
    asm volatile("cp.async.wait_group %0;" :: "n"(N) : "memory");
}

#define LDSM_X4(r, addr)                                                      \
    asm volatile("ldmatrix.sync.aligned.m8n8.x4.shared.b16 {%0,%1,%2,%3}, [%4];" \
                 : "=r"((r)[0]), "=r"((r)[1]), "=r"((r)[2]), "=r"((r)[3])     \
                 : "r"(addr))

#define MMA_BF16(d, a, b0, b1)                                                \
    asm volatile("mma.sync.aligned.m16n8k16.row.col.f32.bf16.bf16.f32 "       \
                 "{%0,%1,%2,%3}, {%4,%5,%6,%7}, {%8,%9}, {%0,%1,%2,%3};"      \
                 : "+f"((d)[0]), "+f"((d)[1]), "+f"((d)[2]), "+f"((d)[3])     \
                 : "r"((a)[0]), "r"((a)[1]), "r"((a)[2]), "r"((a)[3]),        \
                   "r"(b0), "r"(b1))

__device__ __forceinline__ uint32_t bf16x2_pack(float lo, float hi) {
    uint32_t r;
    asm("cvt.rn.bf16x2.f32 %0, %1, %2;" : "=r"(r) : "f"(hi), "f"(lo));
    return r;
}

// ---------------------------------------------------------------------------
// split x (fp32) -> hi/lo bf16
// ---------------------------------------------------------------------------
__global__ void split_kernel(const float* __restrict__ in,
                             __nv_bfloat16* __restrict__ hi,
                             __nv_bfloat16* __restrict__ lo, int n4)
{
    int i = blockIdx.x * blockDim.x + threadIdx.x;
    if (i >= n4) return;
    float4 v = ((const float4*)in)[i];
    __nv_bfloat16 h0 = __float2bfloat16(v.x), h1 = __float2bfloat16(v.y);
    __nv_bfloat16 h2 = __float2bfloat16(v.z), h3 = __float2bfloat16(v.w);
    __nv_bfloat16 l0 = __float2bfloat16(v.x - __bfloat162float(h0));
    __nv_bfloat16 l1 = __float2bfloat16(v.y - __bfloat162float(h1));
    __nv_bfloat16 l2 = __float2bfloat16(v.z - __bfloat162float(h2));
    __nv_bfloat16 l3 = __float2bfloat16(v.w - __bfloat162float(h3));
    __nv_bfloat162* hp = (__nv_bfloat162*)(hi + (size_t)i * 4);
    __nv_bfloat162* lp = (__nv_bfloat162*)(lo + (size_t)i * 4);
    hp[0] = {h0, h1}; hp[1] = {h2, h3};
    lp[0] = {l0, l1}; lp[1] = {l2, l3};
}

// ---------------------------------------------------------------------------
// transpose W[K,N] -> Wt[N,K] split into hi/lo bf16
// ---------------------------------------------------------------------------
__global__ void tsplit_kernel(const float* __restrict__ W,
                              __nv_bfloat16* __restrict__ thi,
                              __nv_bfloat16* __restrict__ tlo, int K, int N)
{
    __shared__ float t[32][33];
    const int kx = blockIdx.y * 32, nx = blockIdx.x * 32;
    const int lx = threadIdx.x & 31, ly = threadIdx.x >> 5;
#pragma unroll
    for (int j = 0; j < 32; j += 8)
        t[ly + j][lx] = W[(size_t)(kx + ly + j) * N + nx + lx];
    __syncthreads();
#pragma unroll
    for (int j = 0; j < 32; j += 8) {
        float v = t[lx][ly + j];
        __nv_bfloat16 h = __float2bfloat16(v);
        __nv_bfloat16 l = __float2bfloat16(v - __bfloat162float(h));
        thi[(size_t)(nx + ly + j) * K + kx + lx] = h;
        tlo[(size_t)(nx + ly + j) * K + kx + lx] = l;
    }
}

// ---------------------------------------------------------------------------
// mma.sync GEMM: C = A[M,512] @ Bt[N,512]^T + bias.  3-stage cp.async.
// 128x128 tile, Kc=64, 8 warps (32x64).  Output fp32 or bf16 hi/lo.
// ---------------------------------------------------------------------------
#define GK        512
#define KC        64
#define NCHUNK    (GK / KC)
#define STAGE     65536
#define GM_SMEM   (3 * STAGE)

__global__ __launch_bounds__(256, 1)
void gemm_mma(const __nv_bfloat16* __restrict__ Ahi,
              const __nv_bfloat16* __restrict__ Alo,
              const __nv_bfloat16* __restrict__ Bhi,
              const __nv_bfloat16* __restrict__ Blo,
              const float* __restrict__ bias,
              float* __restrict__ Cf,
              __nv_bfloat16* __restrict__ Chi, __nv_bfloat16* __restrict__ Clo,
              int N, int bf16out)
{
    extern __shared__ char sm[];
    const uint32_t sb = smem_u32(sm);
    const int tid = threadIdx.x, wid = tid >> 5, lane = tid & 31;
    const int wm = wid & 3, wn = wid >> 2;
    const int m0 = blockIdx.y * 128, n0 = blockIdx.x * 128;

    auto load_chunk = [&](int c, int buf) {
        const int k0 = c * KC;
        const uint32_t base = sb + buf * STAGE;
#pragma unroll
        for (int it = 0; it < 4; ++it) {
            const int op = it * 256 + tid;
            const int r = op >> 3, g = op & 7;
            const uint32_t off = SWZ128((uint32_t)(r * 128 + g * 16));
            const size_t giA = (size_t)(m0 + r) * GK + k0 + g * 8;
            const size_t giB = (size_t)(n0 + r) * GK + k0 + g * 8;
            cpa16(base + off,         Ahi + giA);
            cpa16(base + 16384 + off, Alo + giA);
            cpa16(base + 32768 + off, Bhi + giB);
            cpa16(base + 49152 + off, Blo + giB);
        }
        asm volatile("cp.async.commit_group;" ::: "memory");
    };

    float acc[2][8][4];
#pragma unroll
    for (int i = 0; i < 2; ++i)
#pragma unroll
        for (int j = 0; j < 8; ++j)
#pragma unroll
            for (int k = 0; k < 4; ++k) acc[i][j][k] = 0.0f;

    const int a_row = wm * 32 + (lane & 15);
    const int a_kb  = (lane >> 4) * 16;
    const int b_row = wn * 64 + (lane & 7) + ((lane >> 4) << 3);
    const int b_kb  = ((lane >> 3) & 1) * 16;

    load_chunk(0, 0);
    load_chunk(1, 1);

    for (int c = 0; c < NCHUNK; ++c) {
        if (c + 2 < NCHUNK) { load_chunk(c + 2, (c + 2) % 3); cp_wait<2>(); }
        else if (c + 1 < NCHUNK) { cp_wait<1>(); }
        else { cp_wait<0>(); }
        __syncthreads();

        const uint32_t bufb = sb + (c % 3) * STAGE;
#pragma unroll
        for (int g = 0; g < 4; ++g) {
            uint32_t ah[2][4], al[2][4];
#pragma unroll
            for (int mt = 0; mt < 2; ++mt) {
                const uint32_t offA =
                    SWZ128((uint32_t)((a_row + mt * 16) * 128 + g * 32 + a_kb));
                LDSM_X4(ah[mt], bufb + offA);
                LDSM_X4(al[mt], bufb + 16384 + offA);
            }
#pragma unroll
            for (int np = 0; np < 4; ++np) {
                const uint32_t offB =
                    SWZ128((uint32_t)((b_row + np * 16) * 128 + g * 32 + b_kb));
                uint32_t bh[4], bl[4];
                LDSM_X4(bh, bufb + 32768 + offB);
                LDSM_X4(bl, bufb + 49152 + offB);
#pragma unroll
                for (int mt = 0; mt < 2; ++mt) {
                    MMA_BF16(acc[mt][np * 2 + 0], ah[mt], bh[0], bh[1]);
                    MMA_BF16(acc[mt][np * 2 + 0], ah[mt], bl[0], bl[1]);
                    MMA_BF16(acc[mt][np * 2 + 0], al[mt], bh[0], bh[1]);
                    MMA_BF16(acc[mt][np * 2 + 1], ah[mt], bh[2], bh[3]);
                    MMA_BF16(acc[mt][np * 2 + 1], ah[mt], bl[2], bl[3]);
                    MMA_BF16(acc[mt][np * 2 + 1], al[mt], bh[2], bh[3]);
                }
            }
        }
        __syncthreads();
    }

    // ---- epilogue ----
    const int er = lane >> 2, ec = (lane & 3) * 2;
#pragma unroll
    for (int mt = 0; mt < 2; ++mt) {
        const int row = m0 + wm * 32 + mt * 16 + er;
#pragma unroll
        for (int nt = 0; nt < 8; ++nt) {
            const int col = n0 + wn * 64 + nt * 8 + ec;
            const float2 bv = *(const float2*)(bias + col);
            float v00 = acc[mt][nt][0] + bv.x, v01 = acc[mt][nt][1] + bv.y;
            float v10 = acc[mt][nt][2] + bv.x, v11 = acc[mt][nt][3] + bv.y;
            if (bf16out) {
                __nv_bfloat16 h00 = __float2bfloat16(v00), h01 = __float2bfloat16(v01);
                __nv_bfloat16 h10 = __float2bfloat16(v10), h11 = __float2bfloat16(v11);
                *(__nv_bfloat162*)(Chi + (size_t)row * N + col)       = {h00, h01};
                *(__nv_bfloat162*)(Chi + (size_t)(row + 8) * N + col) = {h10, h11};
                __nv_bfloat162 l0 = {__float2bfloat16(v00 - __bfloat162float(h00)),
                                     __float2bfloat16(v01 - __bfloat162float(h01))};
                __nv_bfloat162 l1 = {__float2bfloat16(v10 - __bfloat162float(h10)),
                                     __float2bfloat16(v11 - __bfloat162float(h11))};
                *(__nv_bfloat162*)(Clo + (size_t)row * N + col)       = l0;
                *(__nv_bfloat162*)(Clo + (size_t)(row + 8) * N + col) = l1;
            } else {
                *(float2*)(Cf + (size_t)row * N + col)       = make_float2(v00, v01);
                *(float2*)(Cf + (size_t)(row + 8) * N + col) = make_float2(v10, v11);
            }
        }
    }
}

// ---------------------------------------------------------------------------
// Tensor-core block-local attention.  One block per (window, head).
// 256 threads = 8 warps in 4(m) x 2(n) grid.
// smem: K[256][72] hi/lo, Vt[64][264] hi/lo, Q[64][72] hi/lo (bf16),
//       O[64][68] fp32, pmax/psum[2][64].
// ---------------------------------------------------------------------------
#define KSTR 72
#define VSTR 264
#define QSTR 72
#define OSTR 68
#define OFF_KHI  0
#define OFF_KLO  36864
#define OFF_VHI  73728
#define OFF_VLO  107520
#define OFF_QHI  141312
#define OFF_QLO  150528
#define OFF_O    159744
#define OFF_PMAX 177152
#define OFF_PSUM 177664
#define ATT2_SMEM 178176

__global__ __launch_bounds__(256, 1)
void attn_mma(const __nv_bfloat16* __restrict__ qkh,
              const __nv_bfloat16* __restrict__ qkl,
              const float* __restrict__ bias,
              __nv_bfloat16* __restrict__ ohi,
              __nv_bfloat16* __restrict__ olo)
{
    extern __shared__ char sm[];
    const uint32_t sb = smem_u32(sm);
    float* Osm  = (float*)(sm + OFF_O);
    float* pmax = (float*)(sm + OFF_PMAX);
    float* psum = (float*)(sm + OFF_PSUM);

    const int tid = threadIdx.x, lane = tid & 31, wid = tid >> 5;
    const int wm = wid & 3, wn = wid >> 2;
    const int head = blockIdx.x & 7, win = blockIdx.x >> 3;
    const int tbase = win * 256;
    const float scale = 0.125f;

    // ---- load K[256][64] hi/lo (16B units, coalesced) ----
#pragma unroll
    for (int it = 0; it < 16; ++it) {
        const int idx = it * 256 + tid;
        const int buf = idx >> 11, rem = idx & 2047;
        const int key = rem >> 3, u = rem & 7;
        const __nv_bfloat16* src = (buf ? qkl : qkh) +
            (size_t)(tbase + key) * 1536 + 512 + head * 64 + u * 8;
        char* dst = sm + (buf ? OFF_KLO : OFF_KHI) + key * (KSTR * 2) + u * 16;
        *(uint4*)dst = *(const uint4*)src;
    }
    // ---- load V transposed: Vt[d][key] hi/lo ----
    {
        const int buf = tid >> 7, p = tid & 127;   // key pair (2p, 2p+1)
        const __nv_bfloat16* s0 = (buf ? qkl : qkh) +
            (size_t)(tbase + 2 * p) * 1536 + 1024 + head * 64;
        const __nv_bfloat16* s1 = s0 + 1536;
        char* vt = sm + (buf ? OFF_VLO : OFF_VHI);
#pragma unroll
        for (int u = 0; u < 8; ++u) {
            const uint4 a = *(const uint4*)(s0 + u * 8);
            const uint4 b = *(const uint4*)(s1 + u * 8);
            const unsigned short* ap = (const unsigned short*)&a;
            const unsigned short* bp = (const unsigned short*)&b;
#pragma unroll
            for (int j = 0; j < 8; ++j) {
                const int d = u * 8 + j;
                *(uint32_t*)(vt + d * (VSTR * 2) + p * 4) =
                    (uint32_t)ap[j] | ((uint32_t)bp[j] << 16);
            }
        }
    }
    __syncthreads();

    // lane components for ldmatrix
    const int qa_row = wm * 16 + (lane & 15);
    const int qa_ke  = (lane >> 4) * 8;
    const int kb_rowc = (lane & 7) + ((lane >> 4) << 3);
    const int kb_ke   = ((lane >> 3) & 1) * 8;

    for (int qt = 0; qt < 4; ++qt) {
        // ---- load Q tile [64][64] hi/lo ----
#pragma unroll
        for (int it = 0; it < 4; ++it) {
            const int idx = it * 256 + tid;
            const int buf = idx >> 9, rem = idx & 511;
            const int row = rem >> 3, u = rem & 7;
            const __nv_bfloat16* src = (buf ? qkl : qkh) +
                (size_t)(tbase + qt * 64 + row) * 1536 + head * 64 + u * 8;
            char* dst = sm + (buf ? OFF_QLO : OFF_QHI) + row * (QSTR * 2) + u * 16;
            *(uint4*)dst = *(const uint4*)src;
        }
        __syncthreads();

        // ---- S = Q K^T : warp tile 16 rows x 128 keys ----
        float c[16][4];
#pragma unroll
        for (int i = 0; i < 16; ++i)
#pragma unroll
            for (int j = 0; j < 4; ++j) c[i][j] = 0.0f;

#pragma unroll
        for (int kt = 0; kt < 4; ++kt) {
            uint32_t ah[4], al[4];
            const uint32_t offQ =
                (uint32_t)(qa_row * (QSTR * 2) + kt * 32 + qa_ke * 2);
            LDSM_X4(ah, sb + OFF_QHI + offQ);
            LDSM_X4(al, sb + OFF_QLO + offQ);
#pragma unroll
            for (int nt2 = 0; nt2 < 8; ++nt2) {
                const int krow = wn * 128 + nt2 * 16 + kb_rowc;
                const uint32_t offK =
                    (uint32_t)(krow * (KSTR * 2) + kt * 32 + kb_ke * 2);
                uint32_t bh[4], bl[4];
                LDSM_X4(bh, sb + OFF_KHI + offK);
                LDSM_X4(bl, sb + OFF_KLO + offK);
                MMA_BF16(c[nt2 * 2 + 0], ah, bh[0], bh[1]);
                MMA_BF16(c[nt2 * 2 + 0], ah, bl[0], bl[1]);
                MMA_BF16(c[nt2 * 2 + 0], al, bh[0], bh[1]);
                MMA_BF16(c[nt2 * 2 + 1], ah, bh[2], bh[3]);
                MMA_BF16(c[nt2 * 2 + 1], ah, bl[2], bl[3]);
                MMA_BF16(c[nt2 * 2 + 1], al, bh[2], bh[3]);
            }
        }

        // ---- scale + bias ----
        const float* bb = bias + head * 65536 +
            (size_t)(qt * 64 + wm * 16 + (lane >> 2)) * 256 +
            wn * 128 + (lane & 3) * 2;
#pragma unroll
        for (int nt = 0; nt < 16; ++nt) {
            const float2 b0 = *(const float2*)(bb + nt * 8);
            const float2 b8 = *(const float2*)(bb + 2048 + nt * 8);
            c[nt][0] = c[nt][0] * scale + b0.x;
            c[nt][1] = c[nt][1] * scale + b0.y;
            c[nt][2] = c[nt][2] * scale + b8.x;
            c[nt][3] = c[nt][3] * scale + b8.y;
        }

        // ---- row max (quad shuffle + cross-warp via smem) ----
        float m0 = c[0][0], m8 = c[0][2];
#pragma unroll
        for (int nt = 0; nt < 16; ++nt) {
            m0 = fmaxf(m0, fmaxf(c[nt][0], c[nt][1]));
            m8 = fmaxf(m8, fmaxf(c[nt][2], c[nt][3]));
        }
        m0 = fmaxf(m0, __shfl_xor_sync(0xffffffffu, m0, 1));
        m0 = fmaxf(m0, __shfl_xor_sync(0xffffffffu, m0, 2));
        m8 = fmaxf(m8, __shfl_xor_sync(0xffffffffu, m8, 1));
        m8 = fmaxf(m8, __shfl_xor_sync(0xffffffffu, m8, 2));
        const int r0 = wm * 16 + (lane >> 2);
        if ((lane & 3) == 0) {
            pmax[wn * 64 + r0]     = m0;
            pmax[wn * 64 + r0 + 8] = m8;
        }
        __syncthreads();
        m0 = fmaxf(pmax[r0],     pmax[64 + r0]);
        m8 = fmaxf(pmax[r0 + 8], pmax[64 + r0 + 8]);

        // ---- exp + partial row sums (normalization deferred to epilogue) ----
        float s0 = 0.0f, s8 = 0.0f;
#pragma unroll
        for (int nt = 0; nt < 16; ++nt) {
            c[nt][0] = __expf(c[nt][0] - m0);  s0 += c[nt][0];
            c[nt][1] = __expf(c[nt][1] - m0);  s0 += c[nt][1];
            c[nt][2] = __expf(c[nt][2] - m8);  s8 += c[nt][2];
            c[nt][3] = __expf(c[nt][3] - m8);  s8 += c[nt][3];
        }
        s0 += __shfl_xor_sync(0xffffffffu, s0, 1);
        s0 += __shfl_xor_sync(0xffffffffu, s0, 2);
        s8 += __shfl_xor_sync(0xffffffffu, s8, 1);
        s8 += __shfl_xor_sync(0xffffffffu, s8, 2);
        if ((lane & 3) == 0) {
            psum[wn * 64 + r0]     = s0;
            psum[wn * 64 + r0 + 8] = s8;
        }

        // ---- O = P V : warp tile 16 rows x 64 dims over its 128 keys ----
        float o[8][4];
#pragma unroll
        for (int i = 0; i < 8; ++i)
#pragma unroll
            for (int j = 0; j < 4; ++j) o[i][j] = 0.0f;

#pragma unroll
        for (int kt = 0; kt < 8; ++kt) {
            // pack P fragments (hi/lo) from c[2kt], c[2kt+1]
            uint32_t ph[4], pl[4];
            {
                const float* ce = c[2 * kt];
                const float* co = c[2 * kt + 1];
                float v[8] = {ce[0], ce[1], ce[2], ce[3], co[0], co[1], co[2], co[3]};
                float h[8], l[8];
#pragma unroll
                for (int j = 0; j < 8; ++j) {
                    __nv_bfloat16 hb = __float2bfloat16(v[j]);
                    h[j] = __bfloat162float(hb);
                    l[j] = v[j] - h[j];
                }
                ph[0] = bf16x2_pack(h[0], h[1]);  ph[1] = bf16x2_pack(h[2], h[3]);
                ph[2] = bf16x2_pack(h[4], h[5]);  ph[3] = bf16x2_pack(h[6], h[7]);
                pl[0] = bf16x2_pack(l[0], l[1]);  pl[1] = bf16x2_pack(l[2], l[3]);
                pl[2] = bf16x2_pack(l[4], l[5]);  pl[3] = bf16x2_pack(l[6], l[7]);
            }
#pragma unroll
            for (int nt2 = 0; nt2 < 4; ++nt2) {
                const int drow = nt2 * 16 + kb_rowc;
                const int kelem = wn * 128 + kt * 16 + kb_ke;
                const uint32_t offV = (uint32_t)(drow * (VSTR * 2) + kelem * 2);
                uint32_t bh[4], bl[4];
                LDSM_X4(bh, sb + OFF_VHI + offV);
                LDSM_X4(bl, sb + OFF_VLO + offV);
                MMA_BF16(o[nt2 * 2 + 0], ph, bh[0], bh[1]);
                MMA_BF16(o[nt2 * 2 + 0], ph, bl[0], bl[1]);
                MMA_BF16(o[nt2 * 2 + 0], pl, bh[0], bh[1]);
                MMA_BF16(o[nt2 * 2 + 1], ph, bh[2], bh[3]);
                MMA_BF16(o[nt2 * 2 + 1], ph, bl[2], bl[3]);
                MMA_BF16(o[nt2 * 2 + 1], pl, bh[2], bh[3]);
            }
        }

        // ---- combine the two key-half warps through smem O ----
        if (wn == 0) {
#pragma unroll
            for (int nt = 0; nt < 8; ++nt) {
                const int cc = nt * 8 + (lane & 3) * 2;
                Osm[r0 * OSTR + cc]           = o[nt][0];
                Osm[r0 * OSTR + cc + 1]       = o[nt][1];
                Osm[(r0 + 8) * OSTR + cc]     = o[nt][2];
                Osm[(r0 + 8) * OSTR + cc + 1] = o[nt][3];
            }
        }
        __syncthreads();
        if (wn == 1) {
#pragma unroll
            for (int nt = 0; nt < 8; ++nt) {
                const int cc = nt * 8 + (lane & 3) * 2;
                Osm[r0 * OSTR + cc]           += o[nt][0];
                Osm[r0 * OSTR + cc + 1]       += o[nt][1];
                Osm[(r0 + 8) * OSTR + cc]     += o[nt][2];
                Osm[(r0 + 8) * OSTR + cc + 1] += o[nt][3];
            }
        }
        __syncthreads();

        // ---- normalize + split hi/lo + store ----
        {
            const int r = tid >> 2, dg = (tid & 3) * 16;
            const float inv = 1.0f / (psum[r] + psum[64 + r]);
            const size_t gb = (size_t)(tbase + qt * 64 + r) * 512 + head * 64 + dg;
#pragma unroll
            for (int j = 0; j < 16; j += 2) {
                const float v0 = Osm[r * OSTR + dg + j] * inv;
                const float v1 = Osm[r * OSTR + dg + j + 1] * inv;
                const __nv_bfloat16 h0 = __float2bfloat16(v0);
                const __nv_bfloat16 h1 = __float2bfloat16(v1);
                *(__nv_bfloat162*)(ohi + gb + j) = {h0, h1};
                *(__nv_bfloat162*)(olo + gb + j) =
                    {__float2bfloat16(v0 - __bfloat162float(h0)),
                     __float2bfloat16(v1 - __bfloat162float(h1))};
            }
        }
        __syncthreads();
    }
}

// ---------------------------------------------------------------------------
extern "C" void kernel_launch(void* const* d_in, const int* in_sizes, int n_in,
                              void* d_out, int out_size)
{
    const float* x     = (const float*)d_in[0];
    const float* Wqkv  = (const float*)d_in[1];
    const float* bqkv  = (const float*)d_in[2];
    const float* Wproj = (const float*)d_in[3];
    const float* bproj = (const float*)d_in[4];
    const float* abias = (const float*)d_in[5];
    float* out = (float*)d_out;

    __nv_bfloat16 *qkh, *qkl, *xhi, *xlo, *ahi, *alo, *wqhi, *wqlo, *wphi, *wplo;
    cudaGetSymbolAddress((void**)&qkh,  g_qkvhi);
    cudaGetSymbolAddress((void**)&qkl,  g_qkvlo);
    cudaGetSymbolAddress((void**)&xhi,  g_xhi);
    cudaGetSymbolAddress((void**)&xlo,  g_xlo);
    cudaGetSymbolAddress((void**)&ahi,  g_ahi);
    cudaGetSymbolAddress((void**)&alo,  g_alo);
    cudaGetSymbolAddress((void**)&wqhi, g_wqhi);
    cudaGetSymbolAddress((void**)&wqlo, g_wqlo);
    cudaGetSymbolAddress((void**)&wphi, g_wphi);
    cudaGetSymbolAddress((void**)&wplo, g_wplo);

    cudaFuncSetAttribute(gemm_mma, cudaFuncAttributeMaxDynamicSharedMemorySize,
                         GM_SMEM);
    cudaFuncSetAttribute(attn_mma, cudaFuncAttributeMaxDynamicSharedMemorySize,
                         ATT2_SMEM);

    const int n4 = 32768 * 512 / 4;
    split_kernel<<<(n4 + 255) / 256, 256>>>(x, xhi, xlo, n4);
    tsplit_kernel<<<dim3(1536 / 32, 512 / 32), 256>>>(Wqkv, wqhi, wqlo, 512, 1536);
    tsplit_kernel<<<dim3(512 / 32, 512 / 32), 256>>>(Wproj, wphi, wplo, 512, 512);

    gemm_mma<<<dim3(12, 256), 256, GM_SMEM>>>(xhi, xlo, wqhi, wqlo, bqkv,
                                              nullptr, qkh, qkl, 1536, 1);
    attn_mma<<<dim3(1024), 256, ATT2_SMEM>>>(qkh, qkl, abias, ahi, alo);
    gemm_mma<<<dim3(4, 256), 256, GM_SMEM>>>(ahi, alo, wphi, wplo, bproj,
                                             out, nullptr, nullptr, 512, 0);
}